// round 11
// baseline (speedup 1.0000x reference)
#include <cuda_runtime.h>
#include <cstdint>

#define NB 64
#define NO 10
#define NI 8000
#define ND 16
#define NE 8

#define ITILE 2
#define NTHR 512                 // pass0 block size
#define NTHRR 704                // routed block size (22 warps, 3 (b,o)-groups each)
#define NSTAGES (NI / ITILE)     // 4000 stages of 2 i's

#define NWITEM (ITILE * NO * 32) // 640 W float4 per stage
#define NXITEM (ITILE * NB * 2)  // 256 x float4 per stage
#define WBUFB (NWITEM * 16)      // pass0: 10240 B per W buffer
#define XBUFB (NXITEM * 16)      // 4096 B per x buffer

// routed W buffer: per (j,o) padded to 33 float4 (528B) for bank spread
#define WSLOT 33
#define NWITEMR (ITILE * NO * WSLOT)  // 660 float4 incl. pad
#define WBUFBR (NWITEMR * 16)         // 10560 B

#define NBLK 148                 // 1 block/SM, one full wave
#define STEPI (NBLK * ITILE)     // i0 advance per grid-stride step = 296

// Scratch (no allocation allowed). g_s zeroed by the fused squash each pass,
// g_ticket reset by the last block -> graph replays are deterministic.
__device__ float g_s[NB * NO * ND] = {};
__device__ float g_v[NB * NO * ND] = {};
__device__ float g_vsum[NB * NO * ND] = {};
__device__ unsigned int g_ticket = 0;

// ---- f32x2 packed math (sm_10x; ptxas won't auto-fuse, must be PTX) ----
__device__ __forceinline__ unsigned long long f2mul(unsigned long long a, unsigned long long b) {
    unsigned long long d;
    asm("mul.rn.f32x2 %0, %1, %2;" : "=l"(d) : "l"(a), "l"(b));
    return d;
}
__device__ __forceinline__ unsigned long long f2fma(unsigned long long a, unsigned long long b, unsigned long long c) {
    unsigned long long d;
    asm("fma.rn.f32x2 %0, %1, %2, %3;" : "=l"(d) : "l"(a), "l"(b), "l"(c));
    return d;
}
__device__ __forceinline__ float f2hadd(unsigned long long a) {
    float lo, hi;
    asm("mov.b64 {%0, %1}, %2;" : "=f"(lo), "=f"(hi) : "l"(a));
    return lo + hi;
}

// ---- cp.async (LDGSTS) helpers ----
__device__ __forceinline__ void cp16(uint32_t dst, const void* src) {
    asm volatile("cp.async.ca.shared.global [%0], [%1], 16;" :: "r"(dst), "l"(src));
}
__device__ __forceinline__ void cp_commit() { asm volatile("cp.async.commit_group;"); }
template <int N>
__device__ __forceinline__ void cp_wait() { asm volatile("cp.async.wait_group %0;" :: "n"(N)); }
__device__ __forceinline__ uint32_t sptr(const void* p) {
    return (uint32_t)__cvta_generic_to_shared(p);
}

// ---- fused squash epilogue (last block); stride-generic over blockDim ----
template <int ITER>
__device__ __forceinline__ void squash_epilogue(int tid, int nthr, float* __restrict__ out)
{
    __threadfence();
    __shared__ unsigned int lastFlag;
    if (tid == 0)
        lastFlag = (atomicAdd(&g_ticket, 1u) == (unsigned)(NBLK - 1)) ? 1u : 0u;
    __syncthreads();
    if (!lastFlag) return;
    __threadfence();  // acquire: all other blocks' atomics are visible

    const float prescale = (ITER == 0) ? 0.1f : 1.0f;
    // nthr is a multiple of 16, so idx-groups of 16 stay warp-aligned and
    // partial tails cover whole warps.
    for (int idx = tid; idx < NB * NO * ND; idx += nthr) {
        float val = g_s[idx] * prescale;
        g_s[idx] = 0.f;
        float n2 = val * val;
        n2 += __shfl_xor_sync(0xffffffffu, n2, 8, 16);
        n2 += __shfl_xor_sync(0xffffffffu, n2, 4, 16);
        n2 += __shfl_xor_sync(0xffffffffu, n2, 2, 16);
        n2 += __shfl_xor_sync(0xffffffffu, n2, 1, 16);
        float norm  = sqrtf(n2);
        float scale = n2 / ((1.f + n2) * (norm + 1e-8f));
        float v = scale * val;
        if (ITER == 0)      { g_v[idx] = v; g_vsum[idx] = v; }
        else if (ITER == 1) { g_v[idx] = v; g_vsum[idx] += v; }
        else                { out[idx] = v; }
    }
    if (tid == 0) g_ticket = 0;  // reset for next pass / next graph replay
}

// ============ PASS 0: (4 batch, 5 o) per thread — unchanged (proven) ============
struct Stager {
    const float4* srcA;
    const float4* srcB;
    uint32_t dstA0, dstB0, bufStrB;
    int srcStepB;
    bool hasB;

    __device__ __forceinline__ void init(int tid, int i00,
                                         const float4* Wf4, const float4* xf4,
                                         uint32_t swbase, uint32_t sxbase) {
        {
            int t = tid;                           // W item < 640
            int j  = t / (NO * 32);
            int r  = t - j * (NO * 32);
            int o  = r >> 5;
            int qg = r & 31;                       // global: d*2 + e4
            int qs = ((qg & 1) << 4) | (qg >> 1);  // shared: e4*16 + d
            srcA  = Wf4 + ((size_t)o * NI + i00 + j) * 32 + qg;
            dstA0 = swbase + (uint32_t)((j * NO + o) * 32 + qs) * 16u;
        }
        hasB = (tid < 384);
        srcB = Wf4; dstB0 = swbase; srcStepB = 0; bufStrB = 0;
        if (tid < 128) {            // W item t = tid+512 in [512,640)
            int t = tid + 512;
            int j  = t / (NO * 32);
            int r  = t - j * (NO * 32);
            int o  = r >> 5;
            int qg = r & 31;
            int qs = ((qg & 1) << 4) | (qg >> 1);
            srcB  = Wf4 + ((size_t)o * NI + i00 + j) * 32 + qg;
            dstB0 = swbase + (uint32_t)((j * NO + o) * 32 + qs) * 16u;
            srcStepB = 32 * STEPI;
            bufStrB  = WBUFB;
        } else if (tid < 384) {     // x item v = tid-128 in [0,256)
            int v = tid - 128;
            int j = v >> 7;
            int r = v & 127;
            int bb = r >> 1;
            int q  = r & 1;
            srcB  = xf4 + ((size_t)bb * NI + i00 + j) * 2 + q;
            dstB0 = sxbase + (uint32_t)((j * NB + bb) * 2 + q) * 16u;
            srcStepB = 2 * STEPI;
            bufStrB  = XBUFB;
        }
    }
    __device__ __forceinline__ void issue(int ib) {
        cp16(dstA0 + (uint32_t)ib * WBUFB, srcA);
        srcA += 32 * STEPI;
        if (hasB) {
            cp16(dstB0 + (uint32_t)ib * bufStrB, srcB);
            srcB += srcStepB;
        }
        cp_commit();
    }
};

__global__ void __launch_bounds__(NTHR, 1)
pass0_kernel(const float* __restrict__ xg, const float* __restrict__ Wg,
             float* __restrict__ out)
{
    __shared__ float4 shW[3][NWITEM];  // 3 x 10 KB
    __shared__ float4 shx[3][NXITEM];  // 3 x 4 KB

    const int tid  = threadIdx.x;
    const int lane = tid & 15;        // d
    const int grp  = tid >> 4;        // 0..31
    const int quad = grp >> 1;        // 0..15 -> batches 4q..4q+3
    const int ob   = (grp & 1) * 5;   // o-half base: 0 or 5

    unsigned long long accp[4][5];
    #pragma unroll
    for (int bb = 0; bb < 4; bb++)
        #pragma unroll
        for (int o = 0; o < 5; o++) accp[bb][o] = 0ull;

    const float4* Wf4 = (const float4*)Wg;
    const float4* xf4 = (const float4*)xg;

    Stager sg;
    sg.init(tid, blockIdx.x * ITILE, Wf4, xf4, sptr(&shW[0][0]), sptr(&shx[0][0]));

    const int st0 = blockIdx.x;
    sg.issue(0);
    if (st0 + NBLK < NSTAGES) sg.issue(1); else cp_commit();

    int parity = 0, inext = 2;
    for (int st = st0; st < NSTAGES; st += NBLK) {
        cp_wait<1>();
        __syncthreads();
        if (st + 2 * NBLK < NSTAGES) sg.issue(inext); else cp_commit();
        inext = (inext + 1 == 3) ? 0 : inext + 1;

        const ulonglong2* shWc = reinterpret_cast<const ulonglong2*>(shW[parity]);
        const ulonglong2* shxc = reinterpret_cast<const ulonglong2*>(shx[parity]);

        #pragma unroll
        for (int j = 0; j < ITILE; j++) {
            ulonglong2 xa[4], xb[4];
            #pragma unroll
            for (int bb = 0; bb < 4; bb++) {
                xa[bb] = shxc[(j * NB + quad * 4 + bb) * 2 + 0];  // e0..3
                xb[bb] = shxc[(j * NB + quad * 4 + bb) * 2 + 1];  // e4..7
            }
            #pragma unroll
            for (int o = 0; o < 5; o++) {
                const int og = ob + o;
                ulonglong2 wa = shWc[(j * NO + og) * 32 + lane];       // e0..3
                ulonglong2 wb = shWc[(j * NO + og) * 32 + 16 + lane];  // e4..7
                #pragma unroll
                for (int bb = 0; bb < 4; bb++) {
                    accp[bb][o] = f2fma(wa.x, xa[bb].x, accp[bb][o]);
                    accp[bb][o] = f2fma(wa.y, xa[bb].y, accp[bb][o]);
                    accp[bb][o] = f2fma(wb.x, xb[bb].x, accp[bb][o]);
                    accp[bb][o] = f2fma(wb.y, xb[bb].y, accp[bb][o]);
                }
            }
        }
        parity = (parity + 1 == 3) ? 0 : parity + 1;
    }

    #pragma unroll
    for (int bb = 0; bb < 4; bb++)
        #pragma unroll
        for (int o = 0; o < 5; o++)
            atomicAdd(&g_s[((quad * 4 + bb) * NO + ob + o) * ND + lane],
                      f2hadd(accp[bb][o]));

    squash_epilogue<0>(tid, NTHR, out);
}

// ============ ROUTED PASSES (ITER 1/2): one (b,o) pair per thread ============
// Thread owns all 16 d's of u_hat[b,o,i,:] in registers -> the agreement dot
// and acc update are THREAD-LOCAL (no shuffles); softmax needs only a 10-lane
// sum (4 shfl_down + 1 broadcast). Warp = 3 groups of 10 lanes (+2 idle).
// W smem per (j,o) padded to 33 float4 so the 10 distinct o-addresses of each
// LDS.128 spread across banks (2 phases/instr).
template <int ITER>
__global__ void __launch_bounds__(NTHRR, 1)
pass_kernel(const float* __restrict__ xg, const float* __restrict__ Wg,
            float* __restrict__ out)
{
    __shared__ float4 shW[3][NWITEMR];  // 3 x 10560 B (padded)
    __shared__ float4 shx[3][NXITEM];   // 3 x 4096 B

    const int tid  = threadIdx.x;
    const int wid  = tid >> 5;
    const int l32  = tid & 31;
    const int gidx = l32 / 10;            // group in warp: 0,1,2 (3 = idle lanes)
    const int r    = l32 - gidx * 10;     // rank within group == o
    const int o    = (gidx < 3) ? r : (l32 - 30);  // idle lanes: harmless o
    int b = wid * 3 + gidx;               // 0..65 (+idle)
    const bool active = (gidx < 3) && (b < NB);
    if (b >= NB) b = NB - 1;              // clamp for safe (duplicate) reads
    const int baseLane = gidx * 10;       // broadcast source (idle: 30 unused)

    float vr[ND], acc[ND];
    {
        const float* vin = (ITER == 1) ? g_v : g_vsum;
        #pragma unroll
        for (int d = 0; d < ND; d++) {
            vr[d] = vin[(b * NO + o) * ND + d];
            acc[d] = 0.f;
        }
    }

    const float4* Wf4 = (const float4*)Wg;
    const float4* xf4 = (const float4*)xg;
    const uint32_t swbase = sptr(&shW[0][0]);
    const uint32_t sxbase = sptr(&shx[0][0]);

    // ---- staging: 896 items, 704 threads; A = all, B = tid<192 ----
    const int i00 = blockIdx.x * ITILE;
    const float4* srcA;
    uint32_t dstA0;
    int srcStepA;
    uint32_t bufStrA;
    if (tid < NWITEM) {                    // W item t = tid (layout: NO permute)
        int t = tid;
        int j  = t / (NO * 32);
        int rr = t - j * (NO * 32);
        int oo = rr >> 5;
        int q  = rr & 31;                  // float4 idx = d*2 + e4 (as in gmem)
        srcA  = Wf4 + ((size_t)oo * NI + i00 + j) * 32 + q;
        dstA0 = swbase + (uint32_t)((j * NO + oo) * WSLOT + q) * 16u;
        srcStepA = 32 * STEPI;
        bufStrA  = WBUFBR;
    } else {                               // x item v = tid-640 in [0,64): j=0
        int v = tid - NWITEM;
        int bb = v >> 1;
        int q  = v & 1;
        srcA  = xf4 + ((size_t)bb * NI + i00) * 2 + q;
        dstA0 = sxbase + (uint32_t)(bb * 2 + q) * 16u;
        srcStepA = 2 * STEPI;
        bufStrA  = XBUFB;
    }
    const bool hasB = (tid < 192);
    const float4* srcB = xf4;
    uint32_t dstB0 = sxbase;
    if (hasB) {                            // x item v = tid+64 in [64,256)
        int v = tid + 64;
        int j  = v >> 7;
        int rr = v & 127;
        int bb = rr >> 1;
        int q  = rr & 1;
        srcB  = xf4 + ((size_t)bb * NI + i00 + j) * 2 + q;
        dstB0 = sxbase + (uint32_t)((j * NB + bb) * 2 + q) * 16u;
    }

    auto issue = [&](int ib) {
        cp16(dstA0 + (uint32_t)ib * bufStrA, srcA);
        srcA += srcStepA;
        if (hasB) {
            cp16(dstB0 + (uint32_t)ib * XBUFB, srcB);
            srcB += 2 * STEPI;
        }
        cp_commit();
    };

    const int st0 = blockIdx.x;
    issue(0);
    if (st0 + NBLK < NSTAGES) issue(1); else cp_commit();

    int parity = 0, inext = 2;
    for (int st = st0; st < NSTAGES; st += NBLK) {
        cp_wait<1>();
        __syncthreads();
        if (st + 2 * NBLK < NSTAGES) issue(inext); else cp_commit();
        inext = (inext + 1 == 3) ? 0 : inext + 1;

        const ulonglong2* shWc = reinterpret_cast<const ulonglong2*>(shW[parity]);
        const ulonglong2* shxc = reinterpret_cast<const ulonglong2*>(shx[parity]);

        #pragma unroll
        for (int j = 0; j < ITILE; j++) {
            // this thread's x (3 lanes per b share -> broadcast)
            ulonglong2 xl = shxc[(j * NB + b) * 2 + 0];  // (e0,e1),(e2,e3)
            ulonglong2 xh = shxc[(j * NB + b) * 2 + 1];  // (e4,e5),(e6,e7)

            const int wb0 = (j * NO + o) * WSLOT;  // float4 units
            float u[ND];
            #pragma unroll
            for (int d = 0; d < ND; d++) {
                ulonglong2 wa = shWc[wb0 + d * 2];      // (w_d,e0..3)
                ulonglong2 wbv = shWc[wb0 + d * 2 + 1]; // (w_d,e4..7)
                unsigned long long t = f2mul(wa.x, xl.x);
                t = f2fma(wa.y, xl.y, t);
                t = f2fma(wbv.x, xh.x, t);
                t = f2fma(wbv.y, xh.y, t);
                u[d] = f2hadd(t);
            }

            // agreement dot (thread-local), 4 independent chains
            float a0 = u[0] * vr[0], a1 = u[1] * vr[1];
            float a2 = u[2] * vr[2], a3 = u[3] * vr[3];
            #pragma unroll
            for (int k = 1; k < 4; k++) {
                a0 = fmaf(u[4 * k + 0], vr[4 * k + 0], a0);
                a1 = fmaf(u[4 * k + 1], vr[4 * k + 1], a1);
                a2 = fmaf(u[4 * k + 2], vr[4 * k + 2], a2);
                a3 = fmaf(u[4 * k + 3], vr[4 * k + 3], a3);
            }
            float a = (a0 + a1) + (a2 + a3);

            // softmax over the 10 o-lanes of this group (logits tiny -> no max)
            float e = __expf(a);
            float s = e;
            float t5 = __shfl_down_sync(0xffffffffu, s, 5);
            if (r < 5) s += t5;                       // r0..4: (r, r+5)
            float t2 = __shfl_down_sync(0xffffffffu, s, 2);
            if (r < 2) s += t2;                       // r0:(0,5,2,7) r1:(1,6,3,8)
            float t1 = __shfl_down_sync(0xffffffffu, s, 1);
            if (r == 0) s += t1;                      // + (1,6,3,8)
            float t4 = __shfl_down_sync(0xffffffffu, s, 4);
            if (r == 0) s += t4;                      // + (4,9) -> all 10
            float m = __shfl_sync(0xffffffffu, s, baseLane);
            float c = __fdividef(e, m);

            #pragma unroll
            for (int d = 0; d < ND; d++)
                acc[d] = fmaf(c, u[d], acc[d]);
        }
        parity = (parity + 1 == 3) ? 0 : parity + 1;
    }

    if (active) {
        #pragma unroll
        for (int d = 0; d < ND; d++)
            atomicAdd(&g_s[(b * NO + o) * ND + d], acc[d]);
    }

    squash_epilogue<ITER>(tid, NTHRR, out);
}

extern "C" void kernel_launch(void* const* d_in, const int* in_sizes, int n_in,
                              void* d_out, int out_size)
{
    const float* x = (const float*)d_in[0];  // [64, 8000, 8]
    const float* W = (const float*)d_in[1];  // [10, 8000, 16, 8]
    float* out = (float*)d_out;              // [64, 10, 16]

    pass0_kernel<<<NBLK, NTHR>>>(x, W, out);     // uniform c=0.1 (in prescale)
    pass_kernel<1><<<NBLK, NTHRR>>>(x, W, out);  // c = softmax_o(u.v0)
    pass_kernel<2><<<NBLK, NTHRR>>>(x, W, out);  // c = softmax_o(u.(v0+v1))
}

// round 12
// speedup vs baseline: 1.9860x; 1.9860x over previous
#include <cuda_runtime.h>
#include <cstdint>

#define NB 64
#define NO 10
#define NI 8000
#define ND 16
#define NE 8

#define ITILE 2
#define NTHR 512
#define NSTAGES (NI / ITILE)     // 4000 stages of 2 i's

#define NWITEM (ITILE * NO * 32) // 640 W float4 per stage
#define NXITEM (ITILE * NB * 2)  // 256 x float4 per stage
#define WBUFB (NWITEM * 16)      // 10240 B per W buffer
#define XBUFB (NXITEM * 16)      // 4096 B per x buffer

#define NBLK 148                 // 1 block/SM, one full wave
#define STEPI (NBLK * ITILE)     // i0 advance per grid-stride step = 296

// Scratch (no allocation allowed). g_s zeroed by the fused squash each pass,
// g_ticket reset by the last block -> graph replays are deterministic.
__device__ float g_s[NB * NO * ND] = {};
__device__ float g_v[NB * NO * ND] = {};
__device__ float g_vsum[NB * NO * ND] = {};
__device__ unsigned int g_ticket = 0;

// ---- f32x2 packed math (sm_10x; ptxas won't auto-fuse, must be PTX) ----
__device__ __forceinline__ unsigned long long f2mul(unsigned long long a, unsigned long long b) {
    unsigned long long d;
    asm("mul.rn.f32x2 %0, %1, %2;" : "=l"(d) : "l"(a), "l"(b));
    return d;
}
__device__ __forceinline__ unsigned long long f2fma(unsigned long long a, unsigned long long b, unsigned long long c) {
    unsigned long long d;
    asm("fma.rn.f32x2 %0, %1, %2, %3;" : "=l"(d) : "l"(a), "l"(b), "l"(c));
    return d;
}
__device__ __forceinline__ float f2hadd(unsigned long long a) {
    float lo, hi;
    asm("mov.b64 {%0, %1}, %2;" : "=f"(lo), "=f"(hi) : "l"(a));
    return lo + hi;
}

// ---- cp.async (LDGSTS) helpers ----
__device__ __forceinline__ void cp16(uint32_t dst, const void* src) {
    asm volatile("cp.async.ca.shared.global [%0], [%1], 16;" :: "r"(dst), "l"(src));
}
__device__ __forceinline__ void cp_commit() { asm volatile("cp.async.commit_group;"); }
template <int N>
__device__ __forceinline__ void cp_wait() { asm volatile("cp.async.wait_group %0;" :: "n"(N)); }
__device__ __forceinline__ uint32_t sptr(const void* p) {
    return (uint32_t)__cvta_generic_to_shared(p);
}

// ---- shared staging descriptor (same smem image for all passes) ----
// shW per (j,o): 32 float4, idx qs = e4*16 + d. shx per (j,b): 2 float4.
struct Stager {
    const float4* srcA;
    const float4* srcB;
    uint32_t dstA0, dstB0, bufStrB;
    int srcStepB;
    bool hasB;

    __device__ __forceinline__ void init(int tid, int i00,
                                         const float4* Wf4, const float4* xf4,
                                         uint32_t swbase, uint32_t sxbase) {
        {
            int t = tid;                           // W item < 640
            int j  = t / (NO * 32);
            int r  = t - j * (NO * 32);
            int o  = r >> 5;
            int qg = r & 31;                       // global: d*2 + e4
            int qs = ((qg & 1) << 4) | (qg >> 1);  // shared: e4*16 + d
            srcA  = Wf4 + ((size_t)o * NI + i00 + j) * 32 + qg;
            dstA0 = swbase + (uint32_t)((j * NO + o) * 32 + qs) * 16u;
        }
        hasB = (tid < 384);
        srcB = Wf4; dstB0 = swbase; srcStepB = 0; bufStrB = 0;
        if (tid < 128) {            // W item t = tid+512 in [512,640)
            int t = tid + 512;
            int j  = t / (NO * 32);
            int r  = t - j * (NO * 32);
            int o  = r >> 5;
            int qg = r & 31;
            int qs = ((qg & 1) << 4) | (qg >> 1);
            srcB  = Wf4 + ((size_t)o * NI + i00 + j) * 32 + qg;
            dstB0 = swbase + (uint32_t)((j * NO + o) * 32 + qs) * 16u;
            srcStepB = 32 * STEPI;
            bufStrB  = WBUFB;
        } else if (tid < 384) {     // x item v = tid-128 in [0,256)
            int v = tid - 128;
            int j = v >> 7;
            int r = v & 127;
            int bb = r >> 1;
            int q  = r & 1;
            srcB  = xf4 + ((size_t)bb * NI + i00 + j) * 2 + q;
            dstB0 = sxbase + (uint32_t)((j * NB + bb) * 2 + q) * 16u;
            srcStepB = 2 * STEPI;
            bufStrB  = XBUFB;
        }
    }
    __device__ __forceinline__ void issue(int ib) {
        cp16(dstA0 + (uint32_t)ib * WBUFB, srcA);
        srcA += 32 * STEPI;
        if (hasB) {
            cp16(dstB0 + (uint32_t)ib * bufStrB, srcB);
            srcB += srcStepB;
        }
        cp_commit();
    }
};

// ---- fused squash epilogue (last block), shared by all passes ----
template <int ITER>
__device__ __forceinline__ void squash_epilogue(int tid, float* __restrict__ out)
{
    __threadfence();
    __shared__ unsigned int lastFlag;
    if (tid == 0)
        lastFlag = (atomicAdd(&g_ticket, 1u) == (unsigned)(NBLK - 1)) ? 1u : 0u;
    __syncthreads();
    if (!lastFlag) return;
    __threadfence();  // acquire: all other blocks' atomics are visible

    const float prescale = (ITER == 0) ? 0.1f : 1.0f;
    #pragma unroll
    for (int k = 0; k < (NB * NO * ND) / NTHR; k++) {
        int idx = k * NTHR + tid;            // idx & 15 == d-lane
        float val = g_s[idx] * prescale;
        g_s[idx] = 0.f;
        float n2 = val * val;
        n2 += __shfl_xor_sync(0xffffffffu, n2, 8, 16);
        n2 += __shfl_xor_sync(0xffffffffu, n2, 4, 16);
        n2 += __shfl_xor_sync(0xffffffffu, n2, 2, 16);
        n2 += __shfl_xor_sync(0xffffffffu, n2, 1, 16);
        float norm  = sqrtf(n2);
        float scale = n2 / ((1.f + n2) * (norm + 1e-8f));
        float v = scale * val;
        if (ITER == 0)      { g_v[idx] = v; g_vsum[idx] = v; }
        else if (ITER == 1) { g_v[idx] = v; g_vsum[idx] += v; }
        else                { out[idx] = v; }
    }
    if (tid == 0) g_ticket = 0;  // reset for next pass / next graph replay
}

// ============ PASS 0: (4 batch, 5 o) per thread — unchanged (proven) ============
__global__ void __launch_bounds__(NTHR, 1)
pass0_kernel(const float* __restrict__ xg, const float* __restrict__ Wg,
             float* __restrict__ out)
{
    __shared__ float4 shW[3][NWITEM];  // 3 x 10 KB
    __shared__ float4 shx[3][NXITEM];  // 3 x 4 KB

    const int tid  = threadIdx.x;
    const int lane = tid & 15;        // d
    const int grp  = tid >> 4;        // 0..31
    const int quad = grp >> 1;        // 0..15 -> batches 4q..4q+3
    const int ob   = (grp & 1) * 5;   // o-half base: 0 or 5

    unsigned long long accp[4][5];
    #pragma unroll
    for (int bb = 0; bb < 4; bb++)
        #pragma unroll
        for (int o = 0; o < 5; o++) accp[bb][o] = 0ull;

    const float4* Wf4 = (const float4*)Wg;
    const float4* xf4 = (const float4*)xg;

    Stager sg;
    sg.init(tid, blockIdx.x * ITILE, Wf4, xf4, sptr(&shW[0][0]), sptr(&shx[0][0]));

    const int st0 = blockIdx.x;
    sg.issue(0);
    if (st0 + NBLK < NSTAGES) sg.issue(1); else cp_commit();

    int parity = 0, inext = 2;
    for (int st = st0; st < NSTAGES; st += NBLK) {
        cp_wait<1>();
        __syncthreads();
        if (st + 2 * NBLK < NSTAGES) sg.issue(inext); else cp_commit();
        inext = (inext + 1 == 3) ? 0 : inext + 1;

        const ulonglong2* shWc = reinterpret_cast<const ulonglong2*>(shW[parity]);
        const ulonglong2* shxc = reinterpret_cast<const ulonglong2*>(shx[parity]);

        #pragma unroll
        for (int j = 0; j < ITILE; j++) {
            ulonglong2 xa[4], xb[4];
            #pragma unroll
            for (int bb = 0; bb < 4; bb++) {
                xa[bb] = shxc[(j * NB + quad * 4 + bb) * 2 + 0];  // e0..3
                xb[bb] = shxc[(j * NB + quad * 4 + bb) * 2 + 1];  // e4..7
            }
            #pragma unroll
            for (int o = 0; o < 5; o++) {
                const int og = ob + o;
                ulonglong2 wa = shWc[(j * NO + og) * 32 + lane];       // e0..3
                ulonglong2 wb = shWc[(j * NO + og) * 32 + 16 + lane];  // e4..7
                #pragma unroll
                for (int bb = 0; bb < 4; bb++) {
                    accp[bb][o] = f2fma(wa.x, xa[bb].x, accp[bb][o]);
                    accp[bb][o] = f2fma(wa.y, xa[bb].y, accp[bb][o]);
                    accp[bb][o] = f2fma(wb.x, xb[bb].x, accp[bb][o]);
                    accp[bb][o] = f2fma(wb.y, xb[bb].y, accp[bb][o]);
                }
            }
        }
        parity = (parity + 1 == 3) ? 0 : parity + 1;
    }

    #pragma unroll
    for (int bb = 0; bb < 4; bb++)
        #pragma unroll
        for (int o = 0; o < 5; o++)
            atomicAdd(&g_s[((quad * 4 + bb) * NO + ob + o) * ND + lane],
                      f2hadd(accp[bb][o]));

    squash_epilogue<0>(tid, out);
}

// ============ ROUTED PASSES (ITER 1/2): o-split layout (R9) ============
// Warp = 4 batches. Half-warp selects o-half: lanes 0-15 -> o in [0,5),
// lanes 16-31 -> o in [5,10); d = lane & 15. Pairing tree leaves lane l
// holding the complete 16-lane agreement sum for o(l) = s2 ? 4 : 2*s4+s8;
// owner lanes {0,8,4,12,2} hold o0..o4. Softmax: broadcast the 5 e's from
// owner lanes (width 16), sum them (= this half's denom part), one xor16
// to add the other half's part -> 13 SHFL/bb instead of 17.
template <int ITER>
__global__ void __launch_bounds__(NTHR, 1)
pass_kernel(const float* __restrict__ xg, const float* __restrict__ Wg,
            float* __restrict__ out)
{
    __shared__ float4 shW[3][NWITEM];
    __shared__ float4 shx[3][NXITEM];

    const int tid  = threadIdx.x;
    const int wid  = tid >> 5;        // warp 0..15
    const int l32  = tid & 31;
    const int d    = tid & 15;        // d-lane
    const int ob   = (l32 >> 4) * 5;  // o-half base: 0 or 5
    const int bq   = wid * 4;         // batch base

    const bool s8 = (d & 8) != 0;
    const bool s4 = (d & 4) != 0;
    const bool s2 = (d & 2) != 0;

    float vr[4][5], acc[4][5];
    {
        const float* vin = (ITER == 1) ? g_v : g_vsum;
        #pragma unroll
        for (int bb = 0; bb < 4; bb++)
            #pragma unroll
            for (int o = 0; o < 5; o++) {
                vr[bb][o] = vin[((bq + bb) * NO + ob + o) * ND + d];
                acc[bb][o] = 0.f;
            }
    }

    const float4* Wf4 = (const float4*)Wg;
    const float4* xf4 = (const float4*)xg;

    Stager sg;
    sg.init(tid, blockIdx.x * ITILE, Wf4, xf4, sptr(&shW[0][0]), sptr(&shx[0][0]));

    const int st0 = blockIdx.x;
    sg.issue(0);
    if (st0 + NBLK < NSTAGES) sg.issue(1); else cp_commit();

    int parity = 0, inext = 2;
    for (int st = st0; st < NSTAGES; st += NBLK) {
        cp_wait<1>();
        __syncthreads();
        if (st + 2 * NBLK < NSTAGES) sg.issue(inext); else cp_commit();
        inext = (inext + 1 == 3) ? 0 : inext + 1;

        const ulonglong2* shWc = reinterpret_cast<const ulonglong2*>(shW[parity]);
        const ulonglong2* shxc = reinterpret_cast<const ulonglong2*>(shx[parity]);

        #pragma unroll
        for (int j = 0; j < ITILE; j++) {
            ulonglong2 xa[4], xb[4];
            #pragma unroll
            for (int bb = 0; bb < 4; bb++) {
                xa[bb] = shxc[(j * NB + bq + bb) * 2 + 0];  // e0..3
                xb[bb] = shxc[(j * NB + bq + bb) * 2 + 1];  // e4..7
            }

            // u[bb][oo] for this half's 5 o's, 4 batches
            float u[4][5];
            #pragma unroll
            for (int oo = 0; oo < 5; oo++) {
                const int og = ob + oo;
                ulonglong2 wa = shWc[(j * NO + og) * 32 + d];
                ulonglong2 wb = shWc[(j * NO + og) * 32 + 16 + d];
                #pragma unroll
                for (int bb = 0; bb < 4; bb++) {
                    unsigned long long t = f2mul(wa.x, xa[bb].x);
                    t = f2fma(wa.y, xa[bb].y, t);
                    t = f2fma(wb.x, xb[bb].x, t);
                    t = f2fma(wb.y, xb[bb].y, t);
                    u[bb][oo] = f2hadd(t);
                }
            }

            // routing per batch: both halves handle their own 5 o's in SIMD
            #pragma unroll
            for (int bb = 0; bb < 4; bb++) {
                float p[5];
                #pragma unroll
                for (int oo = 0; oo < 5; oo++) p[oo] = u[bb][oo] * vr[bb][oo];

                // pairing tree over 16 d-lanes, 5 arrays -> 7 SHFL
                float q0, q1, q2;
                {
                    float keep = s8 ? p[1] : p[0];
                    float send = s8 ? p[0] : p[1];
                    q0 = keep + __shfl_xor_sync(0xffffffffu, send, 8, 16);
                }
                {
                    float keep = s8 ? p[3] : p[2];
                    float send = s8 ? p[2] : p[3];
                    q1 = keep + __shfl_xor_sync(0xffffffffu, send, 8, 16);
                }
                q2 = p[4] + __shfl_xor_sync(0xffffffffu, p[4], 8, 16);
                float r0, r1;
                {
                    float keep = s4 ? q1 : q0;
                    float send = s4 ? q0 : q1;
                    r0 = keep + __shfl_xor_sync(0xffffffffu, send, 4, 16);
                }
                r1 = q2 + __shfl_xor_sync(0xffffffffu, q2, 4, 16);
                float t0;
                {
                    float keep = s2 ? r1 : r0;
                    float send = s2 ? r0 : r1;
                    t0 = keep + __shfl_xor_sync(0xffffffffu, send, 2, 16);
                }
                float a = t0 + __shfl_xor_sync(0xffffffffu, t0, 1, 16);
                // lane holds complete a for o = s2 ? 4 : 2*s4+s8 (local)

                // exp at every lane (logits tiny -> no max subtraction)
                float e = __expf(a);

                // broadcast the 5 e's from owner lanes (this half's o0..o4)
                float e0 = __shfl_sync(0xffffffffu, e, 0, 16);
                float e1 = __shfl_sync(0xffffffffu, e, 8, 16);
                float e2 = __shfl_sync(0xffffffffu, e, 4, 16);
                float e3 = __shfl_sync(0xffffffffu, e, 12, 16);
                float e4 = __shfl_sync(0xffffffffu, e, 2, 16);

                // denominator: this half's sum + other half's sum (xor16)
                float mh = ((e0 + e1) + (e2 + e3)) + e4;
                float m  = mh + __shfl_xor_sync(0xffffffffu, mh, 16);
                float rinv = __fdividef(1.f, m);

                acc[bb][0] = fmaf(e0 * rinv, u[bb][0], acc[bb][0]);
                acc[bb][1] = fmaf(e1 * rinv, u[bb][1], acc[bb][1]);
                acc[bb][2] = fmaf(e2 * rinv, u[bb][2], acc[bb][2]);
                acc[bb][3] = fmaf(e3 * rinv, u[bb][3], acc[bb][3]);
                acc[bb][4] = fmaf(e4 * rinv, u[bb][4], acc[bb][4]);
            }
        }
        parity = (parity + 1 == 3) ? 0 : parity + 1;
    }

    #pragma unroll
    for (int bb = 0; bb < 4; bb++)
        #pragma unroll
        for (int oo = 0; oo < 5; oo++)
            atomicAdd(&g_s[((bq + bb) * NO + ob + oo) * ND + d], acc[bb][oo]);

    squash_epilogue<ITER>(tid, out);
}

extern "C" void kernel_launch(void* const* d_in, const int* in_sizes, int n_in,
                              void* d_out, int out_size)
{
    const float* x = (const float*)d_in[0];  // [64, 8000, 8]
    const float* W = (const float*)d_in[1];  // [10, 8000, 16, 8]
    float* out = (float*)d_out;              // [64, 10, 16]

    pass0_kernel<<<NBLK, NTHR>>>(x, W, out);    // uniform c=0.1 (in prescale)
    pass_kernel<1><<<NBLK, NTHR>>>(x, W, out);  // c = softmax_o(u.v0)
    pass_kernel<2><<<NBLK, NTHR>>>(x, W, out);  // c = softmax_o(u.(v0+v1))
}